// round 1
// baseline (speedup 1.0000x reference)
#include <cuda_runtime.h>

#define H     256
#define H2    128          // H/2 (float2 columns)
#define SEQL  10
#define BQ    2048
#define NTOT  327680
#define NSEG  (BQ * SEQL)  // 20480
#define NENT  20000

// ---------------- scratch (no cudaMalloc allowed) ----------------
__device__ float g_EW1[NENT * H];      // ent_embeds @ W1   (20.5 MB)
__device__ float g_A[BQ * H];          // s@W2 + r@W3 + b   (2 MB)
__device__ float g_scores[NTOT];       // per-neighbor attention score
__device__ int   g_starts[NSEG + 1];   // segment start offsets

// Packed fp32x2 FMA (Blackwell): d = a*b + c on two lanes in one instr.
__device__ __forceinline__ float2 ffma2(float2 a, float2 b, float2 c) {
    float2 d;
    asm("fma.rn.f32x2 %0, %1, %2, %3;"
        : "=l"(reinterpret_cast<unsigned long long&>(d))
        : "l"(reinterpret_cast<const unsigned long long&>(a)),
          "l"(reinterpret_cast<const unsigned long long&>(b)),
          "l"(reinterpret_cast<const unsigned long long&>(c)));
    return d;
}

// ---------------------------------------------------------------------------
// Kernel 1: A[q, :] = s_emb[q] @ W2 + r_emb[q] @ W3 + b
// Block: 128 threads (each owns an h-pair), 8 queries per block, K = 512.
// Shared tile stores each activation value duplicated as float2 so the inner
// loop is 1 broadcast LDS.64 + 1 FFMA2 per (e,k) with zero MOVs.
// ---------------------------------------------------------------------------
__global__ void aq_kernel(const int* __restrict__ s, const int* __restrict__ r,
                          const float* __restrict__ ent, const float* __restrict__ rel,
                          const float* __restrict__ W, const float* __restrict__ b) {
    __shared__ float2 sAd[8 * 512];                   // 32 KB
    const int tid   = threadIdx.x;                    // 0..127
    const int qBase = blockIdx.x * 8;

    for (int idx = tid; idx < 8 * 512; idx += 128) {
        const int e = idx >> 9;
        const int k = idx & 511;
        const int q = qBase + e;
        float val = (k < H) ? ent[(size_t)s[q] * H + k]
                            : rel[(size_t)r[q] * H + (k - H)];
        sAd[idx] = make_float2(val, val);
    }
    __syncthreads();

    const float2 bh = reinterpret_cast<const float2*>(b)[tid];
    float2 acc[8];
#pragma unroll
    for (int e = 0; e < 8; e++) acc[e] = bh;

    const float2* Wf2 = reinterpret_cast<const float2*>(W);
    for (int k = 0; k < 512; k++) {
        const float2 w = Wf2[(size_t)(H + k) * H2 + tid];   // rows 256..767 of W
#pragma unroll
        for (int e = 0; e < 8; e++)
            acc[e] = ffma2(sAd[e * 512 + k], w, acc[e]);
    }

    float2* Aout = reinterpret_cast<float2*>(g_A);
#pragma unroll
    for (int e = 0; e < 8; e++)
        Aout[(size_t)(qBase + e) * H2 + tid] = acc[e];
}

// ---------------------------------------------------------------------------
// Kernel 2: EW1[e, :] = ent_embeds[e] @ W1   (rows 0..255 of W)
// 128 threads, 16 entities per block, K = 256. Same FFMA2 scheme.
// ---------------------------------------------------------------------------
__global__ void ew1_kernel(const float* __restrict__ ent, const float* __restrict__ W) {
    __shared__ float2 sEd[16 * 256];                  // 32 KB
    const int tid   = threadIdx.x;                    // 0..127
    const int eBase = blockIdx.x * 16;

    for (int idx = tid; idx < 16 * 256; idx += 128) {
        const int e = eBase + (idx >> 8);
        float val = (e < NENT) ? ent[(size_t)e * H + (idx & 255)] : 0.0f;
        sEd[idx] = make_float2(val, val);
    }
    __syncthreads();

    float2 acc[16];
#pragma unroll
    for (int e = 0; e < 16; e++) acc[e] = make_float2(0.0f, 0.0f);

    const float2* Wf2 = reinterpret_cast<const float2*>(W);
    for (int k = 0; k < 256; k++) {
        const float2 w = Wf2[(size_t)k * H2 + tid];
#pragma unroll
        for (int e = 0; e < 16; e++)
            acc[e] = ffma2(sEd[e * 256 + k], w, acc[e]);
    }

    float2* Eout = reinterpret_cast<float2*>(g_EW1);
#pragma unroll
    for (int e = 0; e < 16; e++) {
        const int ei = eBase + e;
        if (ei < NENT) Eout[(size_t)ei * H2 + tid] = acc[e];
    }
}

// ---------------------------------------------------------------------------
// Kernel 3: segment start offsets (seg_ids is sorted).
// g_starts[sg] = first i with seg_ids[i] >= sg;  g_starts[NSEG] = NTOT.
// ---------------------------------------------------------------------------
__global__ void starts_kernel(const int* __restrict__ seg_ids) {
    const int i = blockIdx.x * blockDim.x + threadIdx.x;
    if (i >= NTOT) return;
    const int cur  = seg_ids[i];
    const int prev = (i == 0) ? -1 : seg_ids[i - 1];
    for (int sg = prev + 1; sg <= cur; sg++) g_starts[sg] = i;
    if (i == NTOT - 1)
        for (int sg = cur + 1; sg <= NSEG; sg++) g_starts[sg] = NTOT;
}

// ---------------------------------------------------------------------------
// Kernel 4: per-neighbor score = v . tanh(EW1[nbr] + A[q]).  Warp per neighbor.
// ---------------------------------------------------------------------------
__global__ void score_kernel(const int* __restrict__ nbr_ids,
                             const int* __restrict__ seg_ids,
                             const float* __restrict__ v) {
    const int warp = blockIdx.x * 8 + (threadIdx.x >> 5);
    const int lane = threadIdx.x & 31;
    if (warp >= NTOT) return;

    const int nbr = nbr_ids[warp];
    const int q   = seg_ids[warp] / SEQL;

    const float4* ew = reinterpret_cast<const float4*>(g_EW1 + (size_t)nbr * H);
    const float4* aq = reinterpret_cast<const float4*>(g_A + (size_t)q * H);
    const float4* vv = reinterpret_cast<const float4*>(v);

    float sum = 0.0f;
#pragma unroll
    for (int i = 0; i < 2; i++) {
        const int idx = lane + 32 * i;
        const float4 e4 = ew[idx];
        const float4 a4 = aq[idx];
        const float4 v4 = vv[idx];
        sum += tanhf(e4.x + a4.x) * v4.x;
        sum += tanhf(e4.y + a4.y) * v4.y;
        sum += tanhf(e4.z + a4.z) * v4.z;
        sum += tanhf(e4.w + a4.w) * v4.w;
    }
#pragma unroll
    for (int o = 16; o; o >>= 1) sum += __shfl_xor_sync(0xffffffffu, sum, o);
    if (lane == 0) g_scores[warp] = sum;
}

// ---------------------------------------------------------------------------
// Kernel 5: block per segment — softmax over its neighbors, weighted sum of
// neighbor embeddings, and assembly of out[b,t,:] = [agg | s_emb | r_emb]*mask.
// ---------------------------------------------------------------------------
__global__ void agg_kernel(const int* __restrict__ s, const int* __restrict__ r,
                           const int* __restrict__ nbr_ids,
                           const float* __restrict__ ent, const float* __restrict__ rel,
                           float* __restrict__ out) {
    const int seg = blockIdx.x;
    const int tid = threadIdx.x;                      // 0..255, one per h
    const int lo  = g_starts[seg];
    const int hi  = g_starts[seg + 1];

    float* row = out + (size_t)seg * (3 * H);
    if (lo >= hi) {                                   // empty segment -> zeros
        row[tid] = 0.0f; row[H + tid] = 0.0f; row[2 * H + tid] = 0.0f;
        return;
    }
    const int q = seg / SEQL;

    __shared__ float red[8];
    __shared__ float wsm[256];
    __shared__ int   nsm[256];

    // segment max
    float m = -1e30f;
    for (int j = lo + tid; j < hi; j += 256) m = fmaxf(m, g_scores[j]);
#pragma unroll
    for (int o = 16; o; o >>= 1) m = fmaxf(m, __shfl_xor_sync(0xffffffffu, m, o));
    if ((tid & 31) == 0) red[tid >> 5] = m;
    __syncthreads();
    m = red[0];
#pragma unroll
    for (int w = 1; w < 8; w++) m = fmaxf(m, red[w]);

    // segment sum of exp
    float dsum = 0.0f;
    for (int j = lo + tid; j < hi; j += 256) dsum += expf(g_scores[j] - m);
#pragma unroll
    for (int o = 16; o; o >>= 1) dsum += __shfl_xor_sync(0xffffffffu, dsum, o);
    __syncthreads();
    if ((tid & 31) == 0) red[tid >> 5] = dsum;
    __syncthreads();
    dsum = red[0];
#pragma unroll
    for (int w = 1; w < 8; w++) dsum += red[w];
    const float inv = 1.0f / dsum;

    // weighted aggregation of neighbor embeddings
    float acc = 0.0f;
    for (int base = lo; base < hi; base += 256) {
        __syncthreads();
        const int j = base + tid;
        if (j < hi) {
            wsm[tid] = expf(g_scores[j] - m) * inv;
            nsm[tid] = nbr_ids[j];
        }
        __syncthreads();
        const int cnt = min(hi - base, 256);
#pragma unroll 4
        for (int jj = 0; jj < cnt; jj++)
            acc = fmaf(wsm[jj], ent[(size_t)nsm[jj] * H + tid], acc);
    }

    row[tid]         = acc;
    row[H + tid]     = ent[(size_t)s[q] * H + tid];
    row[2 * H + tid] = rel[(size_t)r[q] * H + tid];
}

// ---------------------------------------------------------------------------
extern "C" void kernel_launch(void* const* d_in, const int* in_sizes, int n_in,
                              void* d_out, int out_size) {
    const int*   s    = (const int*)d_in[0];
    const int*   r    = (const int*)d_in[1];
    const int*   nbr  = (const int*)d_in[2];
    const int*   segi = (const int*)d_in[3];
    const float* ent  = (const float*)d_in[4];
    const float* rel  = (const float*)d_in[5];
    const float* W    = (const float*)d_in[6];
    const float* b    = (const float*)d_in[7];
    const float* v    = (const float*)d_in[8];
    float* out = (float*)d_out;

    aq_kernel<<<BQ / 8, 128>>>(s, r, ent, rel, W, b);
    ew1_kernel<<<(NENT + 15) / 16, 128>>>(ent, W);
    starts_kernel<<<(NTOT + 255) / 256, 256>>>(segi);
    score_kernel<<<NTOT / 8, 256>>>(nbr, segi, v);
    agg_kernel<<<NSEG, 256>>>(s, r, nbr, ent, rel, out);
}